// round 1
// baseline (speedup 1.0000x reference)
#include <cuda_runtime.h>

#define FF 40
#define EE 64
#define PP 780            // 40*39/2
#define GG 8              // batch rows per block
#define OUTROW (PP*EE)    // 49920 floats per batch row
#define XROW4 (FF*EE/4)   // 640 float4 per x row

// Precomputed pair products and index tables (written each launch by ffm_init;
// deterministic, allocation-free scratch per harness rules).
__device__ __align__(16) float d_inter[PP * EE];
__device__ int d_pi[PP];
__device__ int d_pj[PP];

// One block per pair p (780 blocks x 64 threads):
// inter[p,e] = fe[i,j,e] * fe[j,i,e], triu row-major order (matches jnp.triu_indices).
__global__ void ffm_init(const float* __restrict__ fe) {
    int p = blockIdx.x;
    int e = threadIdx.x;
    int i = 0, rem = p;
    while (rem >= FF - 1 - i) { rem -= FF - 1 - i; i++; }
    int j = i + 1 + rem;
    d_inter[p * EE + e] = fe[(i * FF + j) * EE + e] * fe[(j * FF + i) * EE + e];
    if (e == 0) { d_pi[p] = i; d_pj[p] = j; }
}

// Main kernel: block handles GG=8 batch rows, all 780 pairs.
// Thread map: t = e4 (16 float4 lanes over E) | g (8 batch rows) | ps (4 pair sub-lanes).
__global__ __launch_bounds__(512, 2)
void ffm_main(const float4* __restrict__ x4, float4* __restrict__ out4) {
    extern __shared__ float4 xs[];            // [GG][XROW4] = 5120 float4 = 80 KB
    const int t = threadIdx.x;
    const size_t b0 = (size_t)blockIdx.x * GG;

    // Stage 8 x rows (coalesced float4 loads, 10 per thread).
    const float4* xin = x4 + b0 * XROW4;
    #pragma unroll
    for (int k = 0; k < (GG * XROW4) / 512; k++)
        xs[t + k * 512] = xin[t + k * 512];
    __syncthreads();

    const int e4 = t & 15;          // float4 index within E=64
    const int g  = (t >> 4) & 7;    // batch row within block
    const int ps = t >> 7;          // pair phase 0..3

    const float4* __restrict__ inter4 = (const float4*)d_inter;
    const float4* __restrict__ xg = xs + g * XROW4;
    float4* __restrict__ orow = out4 + (b0 + g) * (OUTROW / 4);

    #pragma unroll 4
    for (int p = ps; p < PP; p += 4) {
        const int i = d_pi[p];               // uniform per warp -> broadcast LDG
        const int j = d_pj[p];
        const float4 w = inter4[p * 16 + e4];   // L2-resident (200 KB total)
        const float4 a = xg[i * 16 + e4];       // smem, conflict-free
        const float4 b = xg[j * 16 + e4];
        float4 r;
        r.x = a.x * b.x * w.x;
        r.y = a.y * b.y * w.y;
        r.z = a.z * b.z * w.z;
        r.w = a.w * b.w * w.w;
        orow[p * 16 + e4] = r;               // 256B contiguous per (b,p)
    }
}

extern "C" void kernel_launch(void* const* d_in, const int* in_sizes, int n_in,
                              void* d_out, int out_size) {
    // Identify inputs by size: x has 4096*40*64 = 10,485,760 elems,
    // feat_embedding has 40*40*64 = 102,400 elems.
    const float* x;
    const float* fe;
    if (in_sizes[0] > in_sizes[1]) {
        x  = (const float*)d_in[0];
        fe = (const float*)d_in[1];
    } else {
        x  = (const float*)d_in[1];
        fe = (const float*)d_in[0];
    }

    ffm_init<<<PP, EE>>>(fe);

    const size_t smem = (size_t)GG * FF * EE * sizeof(float);   // 81920 B
    cudaFuncSetAttribute(ffm_main, cudaFuncAttributeMaxDynamicSharedMemorySize, (int)smem);
    ffm_main<<<4096 / GG, 512, smem>>>((const float4*)x, (float4*)d_out);
}

// round 2
// speedup vs baseline: 1.5518x; 1.5518x over previous
#include <cuda_runtime.h>

#define FF 40
#define EE 64
#define PP 780              // 40*39/2 pairs
#define GG 4                // batch rows per block
#define PT 130              // pairs per smem tile (780 = 6*130)
#define NTILES (PP / PT)
#define OUTROW4 (PP * EE / 4)   // 12480 float4 per batch row
#define XROW4 (FF * EE / 4)     // 640 float4 per x row
#define THREADS 512

// Scratch written each launch by ffm_init (deterministic, no allocation).
__device__ __align__(16) float d_inter[PP * EE];
__device__ int d_pij[PP];

// inter[p,e] = fe[i,j,e] * fe[j,i,e] in triu row-major pair order.
__global__ void ffm_init(const float* __restrict__ fe) {
    int p = blockIdx.x;
    int e = threadIdx.x;
    int i = 0, rem = p;
    while (rem >= FF - 1 - i) { rem -= FF - 1 - i; i++; }
    int j = i + 1 + rem;
    d_inter[p * EE + e] = fe[(i * FF + j) * EE + e] * fe[(j * FF + i) * EE + e];
    if (e == 0) d_pij[p] = (i << 8) | j;
}

// Block: GG=4 batch rows staged in smem; inter streamed through smem in 6
// tiles of 130 pairs. Inner loop is pure LDS + FMUL + streaming STG.128.
// Thread map: t = e4(16 float4 lanes over E) | g(4 rows) | ps(8 pair phases).
__global__ __launch_bounds__(THREADS, 2)
void ffm_main(const float4* __restrict__ x4, float4* __restrict__ out4) {
    extern __shared__ unsigned char smem_raw[];
    float4* xs   = (float4*)smem_raw;                            // 40960 B
    float4* ws   = (float4*)(smem_raw + GG * XROW4 * 16);        // 33280 B
    int*    spij = (int*)(smem_raw + GG * XROW4 * 16 + PT * 16 * 16);  // 3120 B

    const int t = threadIdx.x;
    const size_t b0 = (size_t)blockIdx.x * GG;

    // Stage 4 x rows (coalesced, evict-first: read exactly once).
    const float4* xin = x4 + b0 * XROW4;
    #pragma unroll
    for (int k = 0; k < (GG * XROW4) / THREADS; k++)      // 5 iters
        xs[t + k * THREADS] = __ldcs(&xin[t + k * THREADS]);
    // Stage packed (i,j) table.
    for (int k = t; k < PP; k += THREADS)
        spij[k] = d_pij[k];

    const int e4 = t & 15;
    const int g  = (t >> 4) & (GG - 1);
    const int ps = t >> 6;                 // 0..7, uniform per warp

    const float4* __restrict__ inter4 = (const float4*)d_inter;
    const float4* __restrict__ xg = xs + g * XROW4;
    float4* __restrict__ orow = out4 + (b0 + g) * OUTROW4;

    for (int tile = 0; tile < NTILES; tile++) {
        const int pbase = tile * PT;
        __syncthreads();                   // ws free (also covers x/pij stage)
        for (int k = t; k < PT * 16; k += THREADS)   // 2080 float4 from L2
            ws[k] = inter4[pbase * 16 + k];
        __syncthreads();                   // ws ready

        #pragma unroll 4
        for (int pr = ps; pr < PT; pr += 8) {
            const int p  = pbase + pr;
            const int ij = spij[p];        // uniform per warp -> broadcast
            const int i  = ij >> 8;
            const int j  = ij & 255;
            const float4 a = xg[i * 16 + e4];
            const float4 b = xg[j * 16 + e4];
            const float4 w = ws[pr * 16 + e4];
            float4 r;
            r.x = a.x * b.x * w.x;
            r.y = a.y * b.y * w.y;
            r.z = a.z * b.z * w.z;
            r.w = a.w * b.w * w.w;
            __stcs(&orow[p * 16 + e4], r); // streaming store, evict-first
        }
    }
}

extern "C" void kernel_launch(void* const* d_in, const int* in_sizes, int n_in,
                              void* d_out, int out_size) {
    // x: 4096*40*64 = 10,485,760 elems; feat_embedding: 40*40*64 = 102,400.
    const float* x;
    const float* fe;
    if (in_sizes[0] > in_sizes[1]) {
        x  = (const float*)d_in[0];
        fe = (const float*)d_in[1];
    } else {
        x  = (const float*)d_in[1];
        fe = (const float*)d_in[0];
    }

    ffm_init<<<PP, EE>>>(fe);

    const int smem = GG * XROW4 * 16 + PT * 16 * 16 + PP * (int)sizeof(int); // 77360
    cudaFuncSetAttribute(ffm_main, cudaFuncAttributeMaxDynamicSharedMemorySize, smem);
    ffm_main<<<4096 / GG, THREADS, smem>>>((const float4*)x, (float4*)d_out);
}

// round 3
// speedup vs baseline: 1.6649x; 1.0729x over previous
#include <cuda_runtime.h>

#define FF 40
#define EE 64
#define PP 780                  // 40*39/2 pairs
#define GG 4                    // batch rows per block
#define OUTROW4 (PP * EE / 4)   // 12480 float4 per batch row
#define XROW4 (FF * EE / 4)     // 640 float4 per x row
#define THREADS 512
#define NTILES 6
#define MAXTP 150               // max pairs in a tile

// Tiles are groups of whole i-rows (row i has 39-i pairs):
//   i in [0,4)=150, [4,8)=134, [8,13)=145, [13,19)=141, [19,27)=132, [27,40)=78
__constant__ int c_istart[NTILES + 1] = {0, 4, 8, 13, 19, 27, 40};
__constant__ int c_pbase [NTILES + 1] = {0, 150, 284, 429, 570, 702, 780};

// Scratch written each launch (deterministic, allocation-free).
__device__ __align__(16) float d_inter[PP * EE];

// inter[p,e] = fe[i,j,e] * fe[j,i,e] in triu row-major pair order.
__global__ void ffm_init(const float* __restrict__ fe) {
    int p = blockIdx.x;
    int e = threadIdx.x;
    int i = 0, rem = p;
    while (rem >= FF - 1 - i) { rem -= FF - 1 - i; i++; }
    int j = i + 1 + rem;
    d_inter[p * EE + e] = fe[(i * FF + j) * EE + e] * fe[(j * FF + i) * EE + e];
}

// Block: GG=4 batch rows staged in smem; inter streamed through smem in 6
// row-aligned tiles. Loop is i-outer (a hoisted, one LDS per row) / j-inner
// (2 LDS + 1 streaming STG per pair).
// Thread map: t = e4(16 float4 lanes over E) | g(4 rows) | ps(8 j-phases).
__global__ __launch_bounds__(THREADS, 2)
void ffm_main(const float4* __restrict__ x4, float4* __restrict__ out4) {
    extern __shared__ unsigned char smem_raw[];
    float4* xs = (float4*)smem_raw;                        // 40960 B
    float4* ws = (float4*)(smem_raw + GG * XROW4 * 16);    // 38400 B

    const int t = threadIdx.x;
    const size_t b0 = (size_t)blockIdx.x * GG;

    // Stage 4 x rows (coalesced, evict-first: read exactly once).
    const float4* xin = x4 + b0 * XROW4;
    #pragma unroll
    for (int k = 0; k < (GG * XROW4) / THREADS; k++)       // 5 iters
        xs[t + k * THREADS] = __ldcs(&xin[t + k * THREADS]);

    const int e4 = t & 15;
    const int g  = (t >> 4) & (GG - 1);
    const int ps = t >> 6;                                 // 0..7, warp-uniform

    const float4* __restrict__ inter4 = (const float4*)d_inter;
    const float4* __restrict__ xg = xs + g * XROW4;
    float4* __restrict__ orow = out4 + (b0 + g) * OUTROW4;

    #pragma unroll
    for (int tile = 0; tile < NTILES; tile++) {
        const int i0 = c_istart[tile];
        const int i1 = c_istart[tile + 1];
        const int pb = c_pbase[tile];
        const int pcnt = c_pbase[tile + 1] - pb;

        __syncthreads();                                   // ws free
        for (int k = t; k < pcnt * 16; k += THREADS)       // from L2 (200 KB res.)
            ws[k] = inter4[pb * 16 + k];
        __syncthreads();                                   // ws ready

        int prow = 0;                                      // tile-local p of (i,i+1)
        for (int i = i0; i < i1; i++) {
            const float4 a = xg[i * 16 + e4];              // one LDS per row
            for (int j = i + 1 + ps; j < FF; j += 8) {
                const int pr = prow + (j - i - 1);
                const float4 b = xg[j * 16 + e4];
                const float4 w = ws[pr * 16 + e4];
                float4 r;
                r.x = a.x * b.x * w.x;
                r.y = a.y * b.y * w.y;
                r.z = a.z * b.z * w.z;
                r.w = a.w * b.w * w.w;
                __stcs(&orow[(pb + pr) * 16 + e4], r);     // evict-first stream
            }
            prow += FF - 1 - i;
        }
    }
}

extern "C" void kernel_launch(void* const* d_in, const int* in_sizes, int n_in,
                              void* d_out, int out_size) {
    // x: 4096*40*64 = 10,485,760 elems; feat_embedding: 40*40*64 = 102,400.
    const float* x;
    const float* fe;
    if (in_sizes[0] > in_sizes[1]) {
        x  = (const float*)d_in[0];
        fe = (const float*)d_in[1];
    } else {
        x  = (const float*)d_in[1];
        fe = (const float*)d_in[0];
    }

    ffm_init<<<PP, EE>>>(fe);

    const int smem = GG * XROW4 * 16 + MAXTP * 16 * 16;    // 79360 B
    cudaFuncSetAttribute(ffm_main, cudaFuncAttributeMaxDynamicSharedMemorySize, smem);
    ffm_main<<<4096 / GG, THREADS, smem>>>((const float4*)x, (float4*)d_out);
}

// round 4
// speedup vs baseline: 1.6948x; 1.0179x over previous
#include <cuda_runtime.h>

#define FF 40
#define EE 64
#define PP 780                  // 40*39/2 pairs
#define GG 4                    // batch rows per block
#define OUTROW4 (PP * EE / 4)   // 12480 float4 per batch row
#define XROW4 (FF * EE / 4)     // 640 float4 per x row
#define THREADS 512
#define NT 5                    // tiles per pair-half
#define MAXTP 102               // max pairs per tile
#define WSSTRIDE (MAXTP * 16)   // float4 stride of one ws buffer

// Row-aligned pair tiles, two halves (blockIdx.y).
// half 0: rows 0..10 (374 pairs); half 1: rows 11..39 (406 pairs).
__constant__ int c_i0[2][NT + 1] = {{0, 2, 4, 7, 10, 11}, {11, 14, 18, 23, 29, 40}};
__constant__ int c_pb[2][NT + 1] = {{0, 77, 150, 252, 345, 374}, {374, 455, 549, 644, 725, 780}};

// Scratch written each launch (deterministic, allocation-free).
__device__ __align__(16) float d_inter[PP * EE];

__device__ __forceinline__ void cpa16(void* dst_smem, const void* src) {
    unsigned d = (unsigned)__cvta_generic_to_shared(dst_smem);
    asm volatile("cp.async.cg.shared.global [%0], [%1], 16;\n" :: "r"(d), "l"(src));
}
#define CPA_COMMIT() asm volatile("cp.async.commit_group;\n" ::: "memory")
#define CPA_WAIT1()  asm volatile("cp.async.wait_group 1;\n" ::: "memory")
#define CPA_WAIT0()  asm volatile("cp.async.wait_group 0;\n" ::: "memory")

// inter[p,e] = fe[i,j,e] * fe[j,i,e] in triu row-major pair order.
__global__ void ffm_init(const float* __restrict__ fe) {
    int p = blockIdx.x;
    int e = threadIdx.x;
    int i = 0, rem = p;
    while (rem >= FF - 1 - i) { rem -= FF - 1 - i; i++; }
    int j = i + 1 + rem;
    d_inter[p * EE + e] = fe[(i * FF + j) * EE + e] * fe[(j * FF + i) * EE + e];
}

// Block (bx, by): batch rows [bx*4, bx*4+4), pair half by.
// x rows staged once in smem; inter tiles double-buffered via cp.async.
// Thread map: t = e4(16) | g(4) | ps(8 warp-uniform j-phases).
__global__ __launch_bounds__(THREADS, 2)
void ffm_main(const float4* __restrict__ x4, float4* __restrict__ out4) {
    extern __shared__ unsigned char smem_raw[];
    float4* xs = (float4*)smem_raw;                          // 40960 B (stride 640/row-group)
    float4* ws = (float4*)(smem_raw + GG * XROW4 * 16);      // 2 x 26112 B

    const int t = threadIdx.x;
    const int half = blockIdx.y;
    const size_t b0 = (size_t)blockIdx.x * GG;
    const int rmin = half ? 11 : 0;                          // first x row needed
    const int xcnt = (FF - rmin) * 16;                       // float4 per staged row

    // Stage x rows [rmin,40) for 4 batch rows (cp.async, part of group 0).
    #pragma unroll
    for (int g = 0; g < GG; g++)
        for (int k = t; k < xcnt; k += THREADS)
            cpa16(&xs[g * XROW4 + k], &x4[(b0 + g) * XROW4 + rmin * 16 + k]);

    const float4* __restrict__ inter4 = (const float4*)d_inter;

    // Fill tile 0 (completes group 0 together with x).
    {
        const int pb = c_pb[half][0];
        const int cnt = (c_pb[half][1] - pb) * 16;
        for (int k = t; k < cnt; k += THREADS)
            cpa16(&ws[k], &inter4[pb * 16 + k]);
    }
    CPA_COMMIT();

    const int e4 = t & 15;
    const int g  = (t >> 4) & (GG - 1);
    const int ps = t >> 6;                                   // 0..7, warp-uniform

    const float4* __restrict__ xg = xs + g * XROW4 - rmin * 16;  // index by true row i
    float4* __restrict__ orow = out4 + (b0 + g) * OUTROW4;

    int cur = 0;
    #pragma unroll
    for (int tile = 0; tile < NT; tile++) {
        if (tile) __syncthreads();           // everyone done with tile-1 compute
        if (tile + 1 < NT) {                 // prefetch next tile into other buffer
            const int pb = c_pb[half][tile + 1];
            const int cnt = (c_pb[half][tile + 2] - pb) * 16;
            float4* buf = ws + (cur ^ 1) * WSSTRIDE;
            for (int k = t; k < cnt; k += THREADS)
                cpa16(&buf[k], &inter4[pb * 16 + k]);
            CPA_COMMIT();
            CPA_WAIT1();                     // current tile's group done
        } else {
            CPA_WAIT0();
        }
        __syncthreads();

        const float4* __restrict__ wbuf = ws + cur * WSSTRIDE;
        const int pb = c_pb[half][tile];
        const int i1 = c_i0[half][tile + 1];
        int prow = 0;
        for (int i = c_i0[half][tile]; i < i1; i++) {
            const float4 a = xg[i * 16 + e4];                // one LDS per row
            const float4* bp = xg + (i + 1 + ps) * 16 + e4;
            const float4* wp = wbuf + (prow + ps) * 16 + e4;
            float4* op = orow + (size_t)(pb + prow + ps) * 16 + e4;
            for (int j = i + 1 + ps; j < FF; j += 8, bp += 128, wp += 128, op += 128) {
                const float4 b = *bp;
                const float4 w = *wp;
                float4 r;
                r.x = a.x * b.x * w.x;
                r.y = a.y * b.y * w.y;
                r.z = a.z * b.z * w.z;
                r.w = a.w * b.w * w.w;
                __stcs(op, r);               // streaming store, evict-first
            }
            prow += FF - 1 - i;
        }
        cur ^= 1;
    }
}

extern "C" void kernel_launch(void* const* d_in, const int* in_sizes, int n_in,
                              void* d_out, int out_size) {
    // x: 4096*40*64 = 10,485,760 elems; feat_embedding: 40*40*64 = 102,400.
    const float* x;
    const float* fe;
    if (in_sizes[0] > in_sizes[1]) {
        x  = (const float*)d_in[0];
        fe = (const float*)d_in[1];
    } else {
        x  = (const float*)d_in[1];
        fe = (const float*)d_in[0];
    }

    ffm_init<<<PP, EE>>>(fe);

    const int smem = GG * XROW4 * 16 + 2 * WSSTRIDE * 16;   // 40960 + 52224 = 93184
    cudaFuncSetAttribute(ffm_main, cudaFuncAttributeMaxDynamicSharedMemorySize, smem);
    dim3 grid(4096 / GG, 2);
    ffm_main<<<grid, THREADS, smem>>>((const float4*)x, (float4*)d_out);
}